// round 16
// baseline (speedup 1.0000x reference)
#include <cuda_runtime.h>

// SpanIndexEncoder: out[t,f] = sum over nodes n (n < num_nodes, start_n <= t <= end_n) of emb[n,f]
// R16: row-level diff array, zeroing moved OUT of the latency-bound output
// kernel into a dedicated store-only kernel at the front of the call.
//   k_zero    : 8 MB STG.128 wipe of g_diff (store roofline, ~1us)
//   k_scatter : low-contention coalesced REDG (+emb at start, -emb at end+1)
//   k_sums    : chunk totals (8 coalesced loads per thread)
//   k_scan    : per-feature shuffle scan -> g_P stored [c][f]
//   k_out     : float2 streaming: P (coalesced LDG.64) + 8 diff rows + scan
//               + 8 coalesced STG.64. NO re-zero stores.
//   T = 8192 tokens, N = 8192 max nodes, F = 256 features, CHUNK = 8.

#define T_MAX  8192
#define N_MAX  8192
#define FDIM   256
#define F2     128               // float2 lanes
#define CHUNK  8
#define NCHUNK (T_MAX / CHUNK)   // 1024

// Scratch (allocation-free). k_zero re-establishes the g_diff zero invariant
// at the start of every call -> graph replays are deterministic.
__device__ float g_diff[T_MAX * FDIM];   // row-level diff array [t][f]
__device__ float g_St[NCHUNK * FDIM];    // chunk totals [c][f]
__device__ float g_P[NCHUNK * FDIM];     // exclusive chunk prefix [c][f]

// ---------------------------------------------------------------------------
// K0: zero the diff array. 2048 blocks x 256 thr x STG.128 = 8 MB wipe.
// ---------------------------------------------------------------------------
__global__ void __launch_bounds__(256) k_zero() {
    int i = blockIdx.x * blockDim.x + threadIdx.x;
    reinterpret_cast<float4*>(g_diff)[i] = make_float4(0.f, 0.f, 0.f, 0.f);
}

// ---------------------------------------------------------------------------
// K1: scatter. One block per node, one thread per feature.
// Coalesced 128B REDG lines, ~1.5 ops/address -> negligible L2-atomic
// serialization (validated R1/R15).
// ---------------------------------------------------------------------------
__global__ void __launch_bounds__(FDIM) k_scatter(const float* __restrict__ emb,
                                                  const int*   __restrict__ starts,
                                                  const int*   __restrict__ ends,
                                                  const int*   __restrict__ num_nodes_p) {
    int n = blockIdx.x;
    if (n >= *num_nodes_p) return;
    int s = starts[n];
    int e = ends[n];
    if (s > e) return;                        // empty span contributes nothing
    int f = threadIdx.x;
    float v = emb[n * FDIM + f];
    atomicAdd(&g_diff[s * FDIM + f], v);
    int e1 = e + 1;
    if (e1 < T_MAX) atomicAdd(&g_diff[e1 * FDIM + f], -v);
}

// ---------------------------------------------------------------------------
// K2: chunk totals. Block c (grid=1024), thread f: 8 independent coalesced
// loads, tree add, one coalesced store. (validated ~1.2us)
// ---------------------------------------------------------------------------
__global__ void __launch_bounds__(FDIM) k_sums() {
    int c = blockIdx.x;
    int f = threadIdx.x;
    const float* db = g_diff + c * CHUNK * FDIM + f;
    float d[CHUNK];
#pragma unroll
    for (int t = 0; t < CHUNK; t++) d[t] = db[t * FDIM];
    g_St[c * FDIM + f] = ((d[0] + d[1]) + (d[2] + d[3]))
                       + ((d[4] + d[5]) + (d[6] + d[7]));
}

// ---------------------------------------------------------------------------
// K3: parallel exclusive prefix over 1024 chunks, per feature.
// Block b = feature (grid=256), 1024 threads; thread j owns chunk j.
// Strided g_St load (L2-resident, hidden by 262K threads), shuffle scan,
// g_P stored [c][f] (scattered 4B fire-and-forget stores) so k_out's
// prefix read is a coalesced float2.
// ---------------------------------------------------------------------------
__global__ void __launch_bounds__(1024) k_scan() {
    int b = blockIdx.x;
    int j = threadIdx.x;
    int lane = j & 31;
    int wid  = j >> 5;

    float v = g_St[j * FDIM + b];             // strided, L2-resident

    float x = v;
#pragma unroll
    for (int d = 1; d < 32; d <<= 1) {
        float u = __shfl_up_sync(0xFFFFFFFFu, x, d);
        if (lane >= d) x += u;
    }

    __shared__ float wsum[32];
    if (lane == 31) wsum[wid] = x;
    __syncthreads();
    if (wid == 0) {
        float y = wsum[lane];
#pragma unroll
        for (int d = 1; d < 32; d <<= 1) {
            float u = __shfl_up_sync(0xFFFFFFFFu, y, d);
            if (lane >= d) y += u;
        }
        wsum[lane] = y;
    }
    __syncthreads();

    float off = (wid > 0) ? wsum[wid - 1] : 0.f;
    g_P[j * FDIM + b] = (x + off) - v;        // exclusive prefix, [c][f]
}

// ---------------------------------------------------------------------------
// K4: streaming output, float2. Grid 512, block 256 = two chunk halves x
// 128 f2-lanes. Per thread: coalesced float2 P load + 8 independent
// coalesced LDG.64 diff loads + 8-row inclusive scan + 8 coalesced STG.64.
// No zero stores (k_zero owns that).
// ---------------------------------------------------------------------------
__global__ void __launch_bounds__(256) k_out(float2* __restrict__ out2) {
    int half = threadIdx.x >> 7;
    int f2   = threadIdx.x & (F2 - 1);
    int c    = blockIdx.x * 2 + half;

    float2 acc = reinterpret_cast<const float2*>(g_P)[c * F2 + f2];   // coalesced
    const float2* db = reinterpret_cast<const float2*>(g_diff) + c * CHUNK * F2 + f2;
    float2*       ob = out2 + c * CHUNK * F2 + f2;

    float2 d[CHUNK];
#pragma unroll
    for (int t = 0; t < CHUNK; t++) d[t] = db[t * F2];    // 8 loads in flight
#pragma unroll
    for (int t = 0; t < CHUNK; t++) {
        acc.x += d[t].x;
        acc.y += d[t].y;
        ob[t * F2] = acc;                                 // coalesced STG.64
    }
}

// ---------------------------------------------------------------------------
// Inputs (metadata order): embedding f32 [8192*256], node_span_starts i32
// [8192], node_span_ends i32 [8192], num_nodes i32 [1]. Output f32 [8192*256].
// ---------------------------------------------------------------------------
extern "C" void kernel_launch(void* const* d_in, const int* in_sizes, int n_in,
                              void* d_out, int out_size) {
    const float* emb    = (const float*)d_in[0];
    const int*   starts = (const int*)d_in[1];
    const int*   ends   = (const int*)d_in[2];
    const int*   nn     = (const int*)d_in[3];
    float2*      out2   = (float2*)d_out;

    k_zero   <<<(T_MAX * FDIM / 4) / 256, 256>>>();
    k_scatter<<<N_MAX, FDIM>>>(emb, starts, ends, nn);
    k_sums   <<<NCHUNK, FDIM>>>();
    k_scan   <<<FDIM, NCHUNK>>>();
    k_out    <<<NCHUNK / 2, 256>>>(out2);
}

// round 17
// speedup vs baseline: 1.0015x; 1.0015x over previous
#include <cuda_runtime.h>

// SpanIndexEncoder: out[t,f] = sum over nodes n (n < num_nodes, start_n <= t <= end_n) of emb[n,f]
// R17: row-level diff array; all transpose cost placed on validated-cheap
// patterns (fire-and-forget scattered stores in k_sums; 2 hidden scalar
// prefix loads in k_out). k_scan is fully coalesced both directions.
//   k_zero    : 8 MB STG.128 wipe of g_diff
//   k_scatter : low-contention coalesced REDG (+emb at start, -emb at end+1)
//   k_sums    : chunk totals; coalesced loads, TRANSPOSED [f][c] stores
//   k_scan    : per-feature shuffle scan, [f][c] coalesced load AND store
//   k_out     : float2 streaming; 2 scalar prefix loads + 8 diff rows + scan
//   T = 8192 tokens, N = 8192 max nodes, F = 256 features, CHUNK = 8.

#define T_MAX  8192
#define N_MAX  8192
#define FDIM   256
#define F2     128               // float2 lanes
#define CHUNK  8
#define NCHUNK (T_MAX / CHUNK)   // 1024

// Scratch (allocation-free). k_zero re-establishes the g_diff zero invariant
// at the start of every call -> graph replays are deterministic.
__device__ float g_diff[T_MAX * FDIM];   // row-level diff array [t][f]
__device__ float g_St[FDIM * NCHUNK];    // chunk totals, TRANSPOSED [f][c]
__device__ float g_Pt[FDIM * NCHUNK];    // exclusive chunk prefix, [f][c]

// ---------------------------------------------------------------------------
// K0: zero the diff array. 2048 blocks x 256 thr x STG.128 = 8 MB wipe.
// ---------------------------------------------------------------------------
__global__ void __launch_bounds__(256) k_zero() {
    int i = blockIdx.x * blockDim.x + threadIdx.x;
    reinterpret_cast<float4*>(g_diff)[i] = make_float4(0.f, 0.f, 0.f, 0.f);
}

// ---------------------------------------------------------------------------
// K1: scatter. One block per node, one thread per feature.
// Coalesced 128B REDG lines, ~1.5 ops/address (validated cheap).
// ---------------------------------------------------------------------------
__global__ void __launch_bounds__(FDIM) k_scatter(const float* __restrict__ emb,
                                                  const int*   __restrict__ starts,
                                                  const int*   __restrict__ ends,
                                                  const int*   __restrict__ num_nodes_p) {
    int n = blockIdx.x;
    if (n >= *num_nodes_p) return;
    int s = starts[n];
    int e = ends[n];
    if (s > e) return;                        // empty span contributes nothing
    int f = threadIdx.x;
    float v = emb[n * FDIM + f];
    atomicAdd(&g_diff[s * FDIM + f], v);
    int e1 = e + 1;
    if (e1 < T_MAX) atomicAdd(&g_diff[e1 * FDIM + f], -v);
}

// ---------------------------------------------------------------------------
// K2: chunk totals. Block c (grid=1024), thread f: 8 independent coalesced
// loads, tree add, ONE scattered 4B store to the transposed layout
// (fire-and-forget; validated acceptable in R5's k_S).
// ---------------------------------------------------------------------------
__global__ void __launch_bounds__(FDIM) k_sums() {
    int c = blockIdx.x;
    int f = threadIdx.x;
    const float* db = g_diff + c * CHUNK * FDIM + f;
    float d[CHUNK];
#pragma unroll
    for (int t = 0; t < CHUNK; t++) d[t] = db[t * FDIM];
    g_St[f * NCHUNK + c] = ((d[0] + d[1]) + (d[2] + d[3]))
                         + ((d[4] + d[5]) + (d[6] + d[7]));
}

// ---------------------------------------------------------------------------
// K3: parallel exclusive prefix over 1024 chunks, per feature (R5-validated,
// FULLY COALESCED). Block b = feature (grid=256), 1024 threads; thread j owns
// chunk j. [f][c] load, shuffle scan + smem warp combine, [f][c] store.
// ---------------------------------------------------------------------------
__global__ void __launch_bounds__(1024) k_scan() {
    int b = blockIdx.x;
    int j = threadIdx.x;
    int lane = j & 31;
    int wid  = j >> 5;

    float v = g_St[b * NCHUNK + j];           // coalesced

    float x = v;
#pragma unroll
    for (int d = 1; d < 32; d <<= 1) {
        float u = __shfl_up_sync(0xFFFFFFFFu, x, d);
        if (lane >= d) x += u;
    }

    __shared__ float wsum[32];
    if (lane == 31) wsum[wid] = x;
    __syncthreads();
    if (wid == 0) {
        float y = wsum[lane];
#pragma unroll
        for (int d = 1; d < 32; d <<= 1) {
            float u = __shfl_up_sync(0xFFFFFFFFu, y, d);
            if (lane >= d) y += u;
        }
        wsum[lane] = y;
    }
    __syncthreads();

    float off = (wid > 0) ? wsum[wid - 1] : 0.f;
    g_Pt[b * NCHUNK + j] = (x + off) - v;     // exclusive prefix, coalesced
}

// ---------------------------------------------------------------------------
// K4: streaming output, float2. Grid 512, block 256 = two chunk halves x
// 128 f2-lanes. Two scalar prefix loads issued FIRST (scattered, hidden
// behind the 8 streaming diff loads), then 8-row inclusive scan + 8
// coalesced STG.64 stores.
// ---------------------------------------------------------------------------
__global__ void __launch_bounds__(256) k_out(float2* __restrict__ out2) {
    int half = threadIdx.x >> 7;
    int f2   = threadIdx.x & (F2 - 1);
    int c    = blockIdx.x * 2 + half;

    float2 acc;
    acc.x = g_Pt[(2 * f2 + 0) * NCHUNK + c];  // scattered scalar, fired early
    acc.y = g_Pt[(2 * f2 + 1) * NCHUNK + c];

    const float2* db = reinterpret_cast<const float2*>(g_diff) + c * CHUNK * F2 + f2;
    float2*       ob = out2 + c * CHUNK * F2 + f2;

    float2 d[CHUNK];
#pragma unroll
    for (int t = 0; t < CHUNK; t++) d[t] = db[t * F2];    // 8 loads in flight
#pragma unroll
    for (int t = 0; t < CHUNK; t++) {
        acc.x += d[t].x;
        acc.y += d[t].y;
        ob[t * F2] = acc;                                 // coalesced STG.64
    }
}

// ---------------------------------------------------------------------------
// Inputs (metadata order): embedding f32 [8192*256], node_span_starts i32
// [8192], node_span_ends i32 [8192], num_nodes i32 [1]. Output f32 [8192*256].
// ---------------------------------------------------------------------------
extern "C" void kernel_launch(void* const* d_in, const int* in_sizes, int n_in,
                              void* d_out, int out_size) {
    const float* emb    = (const float*)d_in[0];
    const int*   starts = (const int*)d_in[1];
    const int*   ends   = (const int*)d_in[2];
    const int*   nn     = (const int*)d_in[3];
    float2*      out2   = (float2*)d_out;

    k_zero   <<<(T_MAX * FDIM / 4) / 256, 256>>>();
    k_scatter<<<N_MAX, FDIM>>>(emb, starts, ends, nn);
    k_sums   <<<NCHUNK, FDIM>>>();
    k_scan   <<<FDIM, NCHUNK>>>();
    k_out    <<<NCHUNK / 2, 256>>>(out2);
}